// round 9
// baseline (speedup 1.0000x reference)
#include <cuda_runtime.h>
#include <math.h>

// SlowMAF via warp-level bf16 mma.sync, 3-term hi/lo split.
// Round 8: m16n8k16 MMAs (native full-rate shape) wherever K allows;
// weight blob reordered so k16 B-fragments load as one LDS.64.
// Inputs (metadata order): x, p0, W1, b1, W2, b2, W3, b3, W4, b4
// Output: [ z (B*32 f32), log_det (B f32) ]

#define BATCH 65536
#define NK 31
#define THREADS 128
#define ROWS_CTA 128      // 4 warps x 2 mtiles x 16 rows
#define MT_PER_WARP 2
#define WBLOB 2192        // u32 per k (see layout map in wprep)

typedef unsigned int u32;
typedef unsigned long long u64;

__device__ u32 g_wblob[NK * WBLOB];
__device__ u32 g_xhi[(size_t)BATCH * 16];
__device__ u32 g_xlo[(size_t)BATCH * 16];

__device__ __forceinline__ void mma8(float d[4], u32 a0, u32 a1, u32 b) {
    asm("mma.sync.aligned.m16n8k8.row.col.f32.bf16.bf16.f32 "
        "{%0,%1,%2,%3}, {%4,%5}, {%6}, {%0,%1,%2,%3};"
        : "+f"(d[0]), "+f"(d[1]), "+f"(d[2]), "+f"(d[3])
        : "r"(a0), "r"(a1), "r"(b));
}
__device__ __forceinline__ void mma16(float d[4], u32 a0, u32 a1, u32 a2, u32 a3,
                                      u32 b0, u32 b1) {
    asm("mma.sync.aligned.m16n8k16.row.col.f32.bf16.bf16.f32 "
        "{%0,%1,%2,%3}, {%4,%5,%6,%7}, {%8,%9}, {%0,%1,%2,%3};"
        : "+f"(d[0]), "+f"(d[1]), "+f"(d[2]), "+f"(d[3])
        : "r"(a0), "r"(a1), "r"(a2), "r"(a3), "r"(b0), "r"(b1));
}

// Split f32 pair (v0=even, v1=odd) into packed bf16x2 hi (truncate) + lo (rn of remainder).
__device__ __forceinline__ void split_pair(float v0, float v1, u32& hi, u32& lo) {
    u32 b0 = __float_as_uint(v0), b1 = __float_as_uint(v1);
    asm("prmt.b32 %0, %1, %2, 0x7632;" : "=r"(hi) : "r"(b0), "r"(b1));
    float l0 = v0 - __uint_as_float(b0 & 0xFFFF0000u);
    float l1 = v1 - __uint_as_float(b1 & 0xFFFF0000u);
    asm("cvt.rn.bf16x2.f32 %0, %1, %2;" : "=r"(lo) : "f"(l1), "f"(l0));
}

__device__ __forceinline__ float lrelu(float v) { return fmaxf(v, 0.2f * v); }

__device__ __forceinline__ void make_frags(const float D[3][4], u32 Ah[3][2], u32 Al[3][2]) {
    #pragma unroll
    for (int nt = 0; nt < 3; nt++) {
        split_pair(lrelu(D[nt][0]), lrelu(D[nt][1]), Ah[nt][0], Al[nt][0]);
        split_pair(lrelu(D[nt][2]), lrelu(D[nt][3]), Ah[nt][1], Al[nt][1]);
    }
}

// ============ prepass: split + fragment-order weights ============
// Blob layout (u32 offsets), per k:
//   w1 pairs:   [0,768)    idx = ((nt*2+p)*2 + cpair)*64 + lw*2 + half
//   w2 pairs:   [768,1152) idx = 768  + (nt*2+p)*64 + lw*2 + c     (c in {0,1})
//   w2 chunk2:  [1152,1344) idx = 1152 + (nt*2+p)*32 + lw
//   w3 pairs:   [1344,1728), w3 chunk2: [1728,1920)  (same structure)
//   w4 pairs:   [1920,2048) idx = 1920 + p*64 + lw*2 + c
//   w4 chunk2:  [2048,2112) idx = 2048 + p*32 + lw
//   biases(f32):[2112,2192) b1|b2|b3|b4pad
__global__ void slowmaf_wprep_kernel(
    const float* __restrict__ W1, const float* __restrict__ b1,
    const float* __restrict__ W2, const float* __restrict__ b2,
    const float* __restrict__ W3, const float* __restrict__ b3,
    const float* __restrict__ W4, const float* __restrict__ b4)
{
    const int k = blockIdx.x;
    const int tid = threadIdx.x;
    u32* blob = g_wblob + k * WBLOB;

    {   // W1: 3nt x 2cpair x 64 entries (hi and lo written together)
        const float* Wk = W1 + (size_t)k * (24 * 32);
        for (int e = tid; e < 3 * 2 * 64; e += THREADS) {
            int nt = e / 128, rem = e % 128;
            int cpair = rem / 64, r = rem % 64;
            int lw = r >> 1, half = r & 1;
            int c = cpair * 2 + half;
            int kk = lw >> 3, n = lw & 7;
            int k0 = c * 8 + kk * 2, ng = nt * 8 + n;
            u32 hi, lo; split_pair(Wk[ng * 32 + k0], Wk[ng * 32 + k0 + 1], hi, lo);
            blob[((nt * 2 + 0) * 2 + cpair) * 64 + r] = hi;
            blob[((nt * 2 + 1) * 2 + cpair) * 64 + r] = lo;
        }
    }
    {   // W2/W3 pairs (chunks 0,1): 3nt x 64
        const float* Wk2 = W2 + (size_t)k * (24 * 24);
        const float* Wk3 = W3 + (size_t)k * (24 * 24);
        for (int e = tid; e < 3 * 64; e += THREADS) {
            int nt = e / 64, r = e % 64;
            int lw = r >> 1, c = r & 1;
            int kk = lw >> 3, n = lw & 7;
            int k0 = c * 8 + kk * 2, ng = nt * 8 + n;
            u32 hi, lo;
            split_pair(Wk2[ng * 24 + k0], Wk2[ng * 24 + k0 + 1], hi, lo);
            blob[768 + (nt * 2 + 0) * 64 + r] = hi;
            blob[768 + (nt * 2 + 1) * 64 + r] = lo;
            split_pair(Wk3[ng * 24 + k0], Wk3[ng * 24 + k0 + 1], hi, lo);
            blob[1344 + (nt * 2 + 0) * 64 + r] = hi;
            blob[1344 + (nt * 2 + 1) * 64 + r] = lo;
        }
        // W2/W3 chunk 2: 3nt x 32
        for (int e = tid; e < 3 * 32; e += THREADS) {
            int nt = e / 32, lw = e % 32;
            int kk = lw >> 3, n = lw & 7;
            int k0 = 16 + kk * 2, ng = nt * 8 + n;
            u32 hi, lo;
            split_pair(Wk2[ng * 24 + k0], Wk2[ng * 24 + k0 + 1], hi, lo);
            blob[1152 + (nt * 2 + 0) * 32 + lw] = hi;
            blob[1152 + (nt * 2 + 1) * 32 + lw] = lo;
            split_pair(Wk3[ng * 24 + k0], Wk3[ng * 24 + k0 + 1], hi, lo);
            blob[1728 + (nt * 2 + 0) * 32 + lw] = hi;
            blob[1728 + (nt * 2 + 1) * 32 + lw] = lo;
        }
    }
    {   // W4 pairs + chunk2 (cols 0=s,1=t, others zero)
        const float* Wk4 = W4 + (size_t)k * (2 * 24);
        for (int e = tid; e < 64; e += THREADS) {
            int lw = e >> 1, c = e & 1;
            int kk = lw >> 3, n = lw & 7;
            int k0 = c * 8 + kk * 2;
            float w0 = (n < 2) ? Wk4[n * 24 + k0] : 0.0f;
            float w1v = (n < 2) ? Wk4[n * 24 + k0 + 1] : 0.0f;
            u32 hi, lo; split_pair(w0, w1v, hi, lo);
            blob[1920 + e] = hi;
            blob[1920 + 64 + e] = lo;
        }
        for (int e = tid; e < 32; e += THREADS) {
            int kk = e >> 3, n = e & 7;
            int k0 = 16 + kk * 2;
            float w0 = (n < 2) ? Wk4[n * 24 + k0] : 0.0f;
            float w1v = (n < 2) ? Wk4[n * 24 + k0 + 1] : 0.0f;
            u32 hi, lo; split_pair(w0, w1v, hi, lo);
            blob[2048 + e] = hi;
            blob[2048 + 32 + e] = lo;
        }
    }
    float* fb = (float*)(blob + 2112);
    if (tid < 24) {
        fb[tid]      = b1[k * 24 + tid];
        fb[24 + tid] = b2[k * 24 + tid];
        fb[48 + tid] = b3[k * 24 + tid];
    }
    if (tid < 8) fb[72 + tid] = (tid < 2) ? b4[k * 2 + tid] : 0.0f;
}

// ---- prepass: split x into hi/lo, fragment-ordered within each row ----
__global__ void slowmaf_xsplit_kernel(const float* __restrict__ x) {
    int p = blockIdx.x * blockDim.x + threadIdx.x;   // < BATCH*16
    int row = p >> 4, cp = p & 15;
    float2 xv = ((const float2*)x)[p];
    u32 hi, lo; split_pair(xv.x, xv.y, hi, lo);
    int dst = (row << 4) + ((cp & 3) << 2) + (cp >> 2);
    g_xhi[dst] = hi;
    g_xlo[dst] = lo;
}

__global__ void slowmaf_init_kernel(const float* __restrict__ x,
                                    const float* __restrict__ p0,
                                    float* __restrict__ z,
                                    float* __restrict__ ld) {
    int row = blockIdx.x * blockDim.x + threadIdx.x;
    float s0 = p0[0];
    z[row * 32 + 31] = x[row * 32] * expf(s0) + p0[1];   // order[0] = 31
    ld[row] = s0;
}

// hidden layer (K=24): mma16 on chunks 0-1, mma8 on chunk 2; 3 passes.
__device__ __forceinline__ void layer_hidden(const u32* wsm, int pairBase, int c2Base,
                                             const float* bs, int lw, int cq,
                                             const u32 Ah[3][2], const u32 Al[3][2],
                                             float D[3][4]) {
    #pragma unroll
    for (int nt = 0; nt < 3; nt++) {
        float q0 = bs[nt * 8 + cq * 2], q1 = bs[nt * 8 + cq * 2 + 1];
        D[nt][0] = q0; D[nt][1] = q1; D[nt][2] = q0; D[nt][3] = q1;
        u64 ph = *(const u64*)(wsm + pairBase + (nt * 2 + 0) * 64 + lw * 2);
        u64 pl = *(const u64*)(wsm + pairBase + (nt * 2 + 1) * 64 + lw * 2);
        u32 c2h = wsm[c2Base + (nt * 2 + 0) * 32 + lw];
        u32 c2l = wsm[c2Base + (nt * 2 + 1) * 32 + lw];
        u32 bh0 = (u32)ph, bh1 = (u32)(ph >> 32);
        u32 bl0 = (u32)pl, bl1 = (u32)(pl >> 32);
        mma16(D[nt], Ah[0][0], Ah[0][1], Ah[1][0], Ah[1][1], bh0, bh1);
        mma8 (D[nt], Ah[2][0], Ah[2][1], c2h);
        mma16(D[nt], Al[0][0], Al[0][1], Al[1][0], Al[1][1], bh0, bh1);
        mma8 (D[nt], Al[2][0], Al[2][1], c2h);
        mma16(D[nt], Ah[0][0], Ah[0][1], Ah[1][0], Ah[1][1], bl0, bl1);
        mma8 (D[nt], Ah[2][0], Ah[2][1], c2l);
    }
}

__global__ __launch_bounds__(THREADS, 6) void slowmaf_hmma_kernel(
    const float* __restrict__ x, float* __restrict__ z, float* __restrict__ ld)
{
    __shared__ __align__(16) u32 wsm[WBLOB];

    const int kidx = blockIdx.y;                 // 0..30
    const int tile = blockIdx.x * ROWS_CTA;
    const int tid  = threadIdx.x;

    {   // copy pre-split weight blob (548 uint4)
        const uint4* src = (const uint4*)(g_wblob + kidx * WBLOB);
        uint4* dst = (uint4*)wsm;
        #pragma unroll
        for (int i = 0; i < 5; i++) {
            int e = i * THREADS + tid;
            if (e < WBLOB / 4) dst[e] = src[e];
        }
    }
    __syncthreads();

    const float* fb  = (const float*)(wsm + 2112);
    const float* b1s = fb, *b2s = fb + 24, *b3s = fb + 48, *b4s = fb + 72;

    const int warp = tid >> 5, lane = tid & 31;
    const int qr = lane >> 2;        // row-in-8 (B-frag n)
    const int cq = lane & 3;         // colpair  (B-frag kk)
    const int lw = cq * 8 + qr;

    #pragma unroll
    for (int mt = 0; mt < MT_PER_WARP; mt++) {
        const int rb = warp * (MT_PER_WARP * 16) + mt * 16;
        const int r0 = rb + qr, r1 = r0 + 8;
        const size_t g0 = ((size_t)(tile + r0) << 4) + (cq << 2);
        const size_t g1 = ((size_t)(tile + r1) << 4) + (cq << 2);

        u32 A1h[4][2], A1l[4][2];
        {
            uint4 H0 = *(const uint4*)(g_xhi + g0);
            uint4 H1 = *(const uint4*)(g_xhi + g1);
            uint4 L0 = *(const uint4*)(g_xlo + g0);
            uint4 L1 = *(const uint4*)(g_xlo + g1);
            A1h[0][0] = H0.x; A1h[1][0] = H0.y; A1h[2][0] = H0.z; A1h[3][0] = H0.w;
            A1h[0][1] = H1.x; A1h[1][1] = H1.y; A1h[2][1] = H1.z; A1h[3][1] = H1.w;
            A1l[0][0] = L0.x; A1l[1][0] = L0.y; A1l[2][0] = L0.z; A1l[3][0] = L0.w;
            A1l[0][1] = L1.x; A1l[1][1] = L1.y; A1l[2][1] = L1.z; A1l[3][1] = L1.w;
        }

        float D[3][4];
        u32 Ah[3][2], Al[3][2];

        // ---- layer 1 (K=32): 2 mma16 per pass per ntile ----
        #pragma unroll
        for (int nt = 0; nt < 3; nt++) {
            float q0 = b1s[nt * 8 + cq * 2], q1 = b1s[nt * 8 + cq * 2 + 1];
            D[nt][0] = q0; D[nt][1] = q1; D[nt][2] = q0; D[nt][3] = q1;
            u64 h0 = *(const u64*)(wsm + ((nt * 2 + 0) * 2 + 0) * 64 + lw * 2);
            u64 h1 = *(const u64*)(wsm + ((nt * 2 + 0) * 2 + 1) * 64 + lw * 2);
            u64 l0 = *(const u64*)(wsm + ((nt * 2 + 1) * 2 + 0) * 64 + lw * 2);
            u64 l1 = *(const u64*)(wsm + ((nt * 2 + 1) * 2 + 1) * 64 + lw * 2);
            mma16(D[nt], A1h[0][0], A1h[0][1], A1h[1][0], A1h[1][1], (u32)h0, (u32)(h0 >> 32));
            mma16(D[nt], A1h[2][0], A1h[2][1], A1h[3][0], A1h[3][1], (u32)h1, (u32)(h1 >> 32));
            mma16(D[nt], A1l[0][0], A1l[0][1], A1l[1][0], A1l[1][1], (u32)h0, (u32)(h0 >> 32));
            mma16(D[nt], A1l[2][0], A1l[2][1], A1l[3][0], A1l[3][1], (u32)h1, (u32)(h1 >> 32));
            mma16(D[nt], A1h[0][0], A1h[0][1], A1h[1][0], A1h[1][1], (u32)l0, (u32)(l0 >> 32));
            mma16(D[nt], A1h[2][0], A1h[2][1], A1h[3][0], A1h[3][1], (u32)l1, (u32)(l1 >> 32));
        }
        make_frags(D, Ah, Al);

        layer_hidden(wsm, 768, 1152, b2s, lw, cq, Ah, Al, D);    // layer 2
        make_frags(D, Ah, Al);
        layer_hidden(wsm, 1344, 1728, b3s, lw, cq, Ah, Al, D);   // layer 3
        make_frags(D, Ah, Al);

        // ---- layer 4: single n-tile (cols 0=s, 1=t) ----
        float E[4];
        {
            float q0 = b4s[cq * 2], q1 = b4s[cq * 2 + 1];
            E[0] = q0; E[1] = q1; E[2] = q0; E[3] = q1;
        }
        {
            u64 ph = *(const u64*)(wsm + 1920 + lw * 2);
            u64 pl = *(const u64*)(wsm + 1920 + 64 + lw * 2);
            u32 c2h = wsm[2048 + lw], c2l = wsm[2048 + 32 + lw];
            u32 bh0 = (u32)ph, bh1 = (u32)(ph >> 32);
            u32 bl0 = (u32)pl, bl1 = (u32)(pl >> 32);
            mma16(E, Ah[0][0], Ah[0][1], Ah[1][0], Ah[1][1], bh0, bh1);
            mma8 (E, Ah[2][0], Ah[2][1], c2h);
            mma16(E, Al[0][0], Al[0][1], Al[1][0], Al[1][1], bh0, bh1);
            mma8 (E, Al[2][0], Al[2][1], c2h);
            mma16(E, Ah[0][0], Ah[0][1], Ah[1][0], Ah[1][1], bl0, bl1);
            mma8 (E, Ah[2][0], Ah[2][1], c2l);
        }

        if (cq == 0) {
            const int kc = kidx + 1;
            #pragma unroll
            for (int half = 0; half < 2; half++) {
                int grow = tile + (half ? r1 : r0);
                float s = E[half * 2], t = E[half * 2 + 1];
                float xv = x[grow * 32 + kc];
                z[grow * 32 + (30 - kidx)] = xv * expf(s) + t;
                atomicAdd(&ld[grow], s);
            }
        }
    }
}

extern "C" void kernel_launch(void* const* d_in, const int* in_sizes, int n_in,
                              void* d_out, int out_size) {
    const float* x  = (const float*)d_in[0];
    const float* p0 = (const float*)d_in[1];
    const float* W1 = (const float*)d_in[2];
    const float* b1 = (const float*)d_in[3];
    const float* W2 = (const float*)d_in[4];
    const float* b2 = (const float*)d_in[5];
    const float* W3 = (const float*)d_in[6];
    const float* b3 = (const float*)d_in[7];
    const float* W4 = (const float*)d_in[8];
    const float* b4 = (const float*)d_in[9];

    float* z  = (float*)d_out;                 // B*32
    float* ld = z + (size_t)BATCH * 32;        // B

    slowmaf_wprep_kernel<<<NK, THREADS>>>(W1, b1, W2, b2, W3, b3, W4, b4);
    slowmaf_xsplit_kernel<<<BATCH * 16 / 256, 256>>>(x);
    slowmaf_init_kernel<<<BATCH / 256, 256>>>(x, p0, z, ld);

    dim3 grid(BATCH / ROWS_CTA, NK);
    slowmaf_hmma_kernel<<<grid, THREADS>>>(x, z, ld);
}

// round 11
// speedup vs baseline: 1.5063x; 1.5063x over previous
#include <cuda_runtime.h>
#include <math.h>

// SlowMAF via warp-level bf16 mma.sync (m16n8k16/k8), 3-term hi/lo split.
// Round 10 (re-run; prior attempt died to container infra): both mtiles
// processed per layer with B fragments loaded once (halves smem B traffic,
// doubles accumulator-chain ILP).
// Inputs (metadata order): x, p0, W1, b1, W2, b2, W3, b3, W4, b4
// Output: [ z (B*32 f32), log_det (B f32) ]

#define BATCH 65536
#define NK 31
#define THREADS 128
#define ROWS_CTA 128      // 4 warps x 2 mtiles x 16 rows
#define WBLOB 2192        // u32 per k (layout map in wprep)

typedef unsigned int u32;
typedef unsigned long long u64;

__device__ u32 g_wblob[NK * WBLOB];
__device__ u32 g_xhi[(size_t)BATCH * 16];
__device__ u32 g_xlo[(size_t)BATCH * 16];

__device__ __forceinline__ void mma8(float d[4], u32 a0, u32 a1, u32 b) {
    asm("mma.sync.aligned.m16n8k8.row.col.f32.bf16.bf16.f32 "
        "{%0,%1,%2,%3}, {%4,%5}, {%6}, {%0,%1,%2,%3};"
        : "+f"(d[0]), "+f"(d[1]), "+f"(d[2]), "+f"(d[3])
        : "r"(a0), "r"(a1), "r"(b));
}
__device__ __forceinline__ void mma16(float d[4], u32 a0, u32 a1, u32 a2, u32 a3,
                                      u32 b0, u32 b1) {
    asm("mma.sync.aligned.m16n8k16.row.col.f32.bf16.bf16.f32 "
        "{%0,%1,%2,%3}, {%4,%5,%6,%7}, {%8,%9}, {%0,%1,%2,%3};"
        : "+f"(d[0]), "+f"(d[1]), "+f"(d[2]), "+f"(d[3])
        : "r"(a0), "r"(a1), "r"(a2), "r"(a3), "r"(b0), "r"(b1));
}

// Split f32 pair (v0=even, v1=odd) into packed bf16x2 hi (truncate) + lo (rn of remainder).
__device__ __forceinline__ void split_pair(float v0, float v1, u32& hi, u32& lo) {
    u32 b0 = __float_as_uint(v0), b1 = __float_as_uint(v1);
    asm("prmt.b32 %0, %1, %2, 0x7632;" : "=r"(hi) : "r"(b0), "r"(b1));
    float l0 = v0 - __uint_as_float(b0 & 0xFFFF0000u);
    float l1 = v1 - __uint_as_float(b1 & 0xFFFF0000u);
    asm("cvt.rn.bf16x2.f32 %0, %1, %2;" : "=r"(lo) : "f"(l1), "f"(l0));
}

__device__ __forceinline__ float lrelu(float v) { return fmaxf(v, 0.2f * v); }

__device__ __forceinline__ void make_frags(const float D[3][4], u32 Ah[3][2], u32 Al[3][2]) {
    #pragma unroll
    for (int nt = 0; nt < 3; nt++) {
        split_pair(lrelu(D[nt][0]), lrelu(D[nt][1]), Ah[nt][0], Al[nt][0]);
        split_pair(lrelu(D[nt][2]), lrelu(D[nt][3]), Ah[nt][1], Al[nt][1]);
    }
}

// ============ prepass: split + fragment-order weights ============
__global__ void slowmaf_wprep_kernel(
    const float* __restrict__ W1, const float* __restrict__ b1,
    const float* __restrict__ W2, const float* __restrict__ b2,
    const float* __restrict__ W3, const float* __restrict__ b3,
    const float* __restrict__ W4, const float* __restrict__ b4)
{
    const int k = blockIdx.x;
    const int tid = threadIdx.x;
    u32* blob = g_wblob + k * WBLOB;

    {   // W1: 3nt x 2cpair x 64
        const float* Wk = W1 + (size_t)k * (24 * 32);
        for (int e = tid; e < 3 * 2 * 64; e += THREADS) {
            int nt = e / 128, rem = e % 128;
            int cpair = rem / 64, r = rem % 64;
            int lw = r >> 1, half = r & 1;
            int c = cpair * 2 + half;
            int kk = lw >> 3, n = lw & 7;
            int k0 = c * 8 + kk * 2, ng = nt * 8 + n;
            u32 hi, lo; split_pair(Wk[ng * 32 + k0], Wk[ng * 32 + k0 + 1], hi, lo);
            blob[((nt * 2 + 0) * 2 + cpair) * 64 + r] = hi;
            blob[((nt * 2 + 1) * 2 + cpair) * 64 + r] = lo;
        }
    }
    {   // W2/W3 pairs (chunks 0,1) + chunk 2
        const float* Wk2 = W2 + (size_t)k * (24 * 24);
        const float* Wk3 = W3 + (size_t)k * (24 * 24);
        for (int e = tid; e < 3 * 64; e += THREADS) {
            int nt = e / 64, r = e % 64;
            int lw = r >> 1, c = r & 1;
            int kk = lw >> 3, n = lw & 7;
            int k0 = c * 8 + kk * 2, ng = nt * 8 + n;
            u32 hi, lo;
            split_pair(Wk2[ng * 24 + k0], Wk2[ng * 24 + k0 + 1], hi, lo);
            blob[768 + (nt * 2 + 0) * 64 + r] = hi;
            blob[768 + (nt * 2 + 1) * 64 + r] = lo;
            split_pair(Wk3[ng * 24 + k0], Wk3[ng * 24 + k0 + 1], hi, lo);
            blob[1344 + (nt * 2 + 0) * 64 + r] = hi;
            blob[1344 + (nt * 2 + 1) * 64 + r] = lo;
        }
        for (int e = tid; e < 3 * 32; e += THREADS) {
            int nt = e / 32, lw = e % 32;
            int kk = lw >> 3, n = lw & 7;
            int k0 = 16 + kk * 2, ng = nt * 8 + n;
            u32 hi, lo;
            split_pair(Wk2[ng * 24 + k0], Wk2[ng * 24 + k0 + 1], hi, lo);
            blob[1152 + (nt * 2 + 0) * 32 + lw] = hi;
            blob[1152 + (nt * 2 + 1) * 32 + lw] = lo;
            split_pair(Wk3[ng * 24 + k0], Wk3[ng * 24 + k0 + 1], hi, lo);
            blob[1728 + (nt * 2 + 0) * 32 + lw] = hi;
            blob[1728 + (nt * 2 + 1) * 32 + lw] = lo;
        }
    }
    {   // W4
        const float* Wk4 = W4 + (size_t)k * (2 * 24);
        for (int e = tid; e < 64; e += THREADS) {
            int lw = e >> 1, c = e & 1;
            int kk = lw >> 3, n = lw & 7;
            int k0 = c * 8 + kk * 2;
            float w0 = (n < 2) ? Wk4[n * 24 + k0] : 0.0f;
            float w1v = (n < 2) ? Wk4[n * 24 + k0 + 1] : 0.0f;
            u32 hi, lo; split_pair(w0, w1v, hi, lo);
            blob[1920 + e] = hi;
            blob[1920 + 64 + e] = lo;
        }
        for (int e = tid; e < 32; e += THREADS) {
            int kk = e >> 3, n = e & 7;
            int k0 = 16 + kk * 2;
            float w0 = (n < 2) ? Wk4[n * 24 + k0] : 0.0f;
            float w1v = (n < 2) ? Wk4[n * 24 + k0 + 1] : 0.0f;
            u32 hi, lo; split_pair(w0, w1v, hi, lo);
            blob[2048 + e] = hi;
            blob[2048 + 32 + e] = lo;
        }
    }
    float* fb = (float*)(blob + 2112);
    if (tid < 24) {
        fb[tid]      = b1[k * 24 + tid];
        fb[24 + tid] = b2[k * 24 + tid];
        fb[48 + tid] = b3[k * 24 + tid];
    }
    if (tid < 8) fb[72 + tid] = (tid < 2) ? b4[k * 2 + tid] : 0.0f;
}

__global__ void slowmaf_xsplit_kernel(const float* __restrict__ x) {
    int p = blockIdx.x * blockDim.x + threadIdx.x;   // < BATCH*16
    int row = p >> 4, cp = p & 15;
    float2 xv = ((const float2*)x)[p];
    u32 hi, lo; split_pair(xv.x, xv.y, hi, lo);
    int dst = (row << 4) + ((cp & 3) << 2) + (cp >> 2);
    g_xhi[dst] = hi;
    g_xlo[dst] = lo;
}

__global__ void slowmaf_init_kernel(const float* __restrict__ x,
                                    const float* __restrict__ p0,
                                    float* __restrict__ z,
                                    float* __restrict__ ld) {
    int row = blockIdx.x * blockDim.x + threadIdx.x;
    float s0 = p0[0];
    z[row * 32 + 31] = x[row * 32] * expf(s0) + p0[1];   // order[0] = 31
    ld[row] = s0;
}

// hidden layer (K=24), BOTH mtiles, B loaded once per nt.
__device__ __forceinline__ void layer_hidden2(
    const u32* wsm, int pairBase, int c2Base, const float* bs, int lw, int cq,
    const u32 Ah0[3][2], const u32 Al0[3][2],
    const u32 Ah1[3][2], const u32 Al1[3][2],
    float D0[3][4], float D1[3][4])
{
    #pragma unroll
    for (int nt = 0; nt < 3; nt++) {
        float q0 = bs[nt * 8 + cq * 2], q1 = bs[nt * 8 + cq * 2 + 1];
        D0[nt][0] = q0; D0[nt][1] = q1; D0[nt][2] = q0; D0[nt][3] = q1;
        D1[nt][0] = q0; D1[nt][1] = q1; D1[nt][2] = q0; D1[nt][3] = q1;
        u64 ph = *(const u64*)(wsm + pairBase + (nt * 2 + 0) * 64 + lw * 2);
        u64 pl = *(const u64*)(wsm + pairBase + (nt * 2 + 1) * 64 + lw * 2);
        u32 c2h = wsm[c2Base + (nt * 2 + 0) * 32 + lw];
        u32 c2l = wsm[c2Base + (nt * 2 + 1) * 32 + lw];
        u32 bh0 = (u32)ph, bh1 = (u32)(ph >> 32);
        u32 bl0 = (u32)pl, bl1 = (u32)(pl >> 32);
        mma16(D0[nt], Ah0[0][0], Ah0[0][1], Ah0[1][0], Ah0[1][1], bh0, bh1);
        mma16(D1[nt], Ah1[0][0], Ah1[0][1], Ah1[1][0], Ah1[1][1], bh0, bh1);
        mma8 (D0[nt], Ah0[2][0], Ah0[2][1], c2h);
        mma8 (D1[nt], Ah1[2][0], Ah1[2][1], c2h);
        mma16(D0[nt], Al0[0][0], Al0[0][1], Al0[1][0], Al0[1][1], bh0, bh1);
        mma16(D1[nt], Al1[0][0], Al1[0][1], Al1[1][0], Al1[1][1], bh0, bh1);
        mma8 (D0[nt], Al0[2][0], Al0[2][1], c2h);
        mma8 (D1[nt], Al1[2][0], Al1[2][1], c2h);
        mma16(D0[nt], Ah0[0][0], Ah0[0][1], Ah0[1][0], Ah0[1][1], bl0, bl1);
        mma16(D1[nt], Ah1[0][0], Ah1[0][1], Ah1[1][0], Ah1[1][1], bl0, bl1);
        mma8 (D0[nt], Ah0[2][0], Ah0[2][1], c2l);
        mma8 (D1[nt], Ah1[2][0], Ah1[2][1], c2l);
    }
}

__global__ __launch_bounds__(THREADS, 5) void slowmaf_hmma_kernel(
    const float* __restrict__ x, float* __restrict__ z, float* __restrict__ ld)
{
    __shared__ __align__(16) u32 wsm[WBLOB];

    const int kidx = blockIdx.y;                 // 0..30
    const int tile = blockIdx.x * ROWS_CTA;
    const int tid  = threadIdx.x;

    {   // copy pre-split weight blob (548 uint4)
        const uint4* src = (const uint4*)(g_wblob + kidx * WBLOB);
        uint4* dst = (uint4*)wsm;
        #pragma unroll
        for (int i = 0; i < 5; i++) {
            int e = i * THREADS + tid;
            if (e < WBLOB / 4) dst[e] = src[e];
        }
    }
    __syncthreads();

    const float* fb  = (const float*)(wsm + 2112);
    const float* b1s = fb, *b2s = fb + 24, *b3s = fb + 48, *b4s = fb + 72;

    const int warp = tid >> 5, lane = tid & 31;
    const int qr = lane >> 2;        // row-in-8 (B-frag n)
    const int cq = lane & 3;         // colpair  (B-frag kk)
    const int lw = cq * 8 + qr;

    const int rb = warp * 32;
    const int r0 = rb + qr,      r1 = r0 + 8;     // mtile 0
    const int r2 = rb + 16 + qr, r3 = r2 + 8;     // mtile 1

    // ---- A fragments for layer 1, both mtiles ----
    u32 A1h0[4][2], A1l0[4][2], A1h1[4][2], A1l1[4][2];
    {
        const size_t g0 = ((size_t)(tile + r0) << 4) + (cq << 2);
        const size_t g1 = ((size_t)(tile + r1) << 4) + (cq << 2);
        const size_t g2 = ((size_t)(tile + r2) << 4) + (cq << 2);
        const size_t g3 = ((size_t)(tile + r3) << 4) + (cq << 2);
        uint4 H0 = *(const uint4*)(g_xhi + g0), H1 = *(const uint4*)(g_xhi + g1);
        uint4 L0 = *(const uint4*)(g_xlo + g0), L1 = *(const uint4*)(g_xlo + g1);
        uint4 H2 = *(const uint4*)(g_xhi + g2), H3 = *(const uint4*)(g_xhi + g3);
        uint4 L2 = *(const uint4*)(g_xlo + g2), L3 = *(const uint4*)(g_xlo + g3);
        A1h0[0][0]=H0.x; A1h0[1][0]=H0.y; A1h0[2][0]=H0.z; A1h0[3][0]=H0.w;
        A1h0[0][1]=H1.x; A1h0[1][1]=H1.y; A1h0[2][1]=H1.z; A1h0[3][1]=H1.w;
        A1l0[0][0]=L0.x; A1l0[1][0]=L0.y; A1l0[2][0]=L0.z; A1l0[3][0]=L0.w;
        A1l0[0][1]=L1.x; A1l0[1][1]=L1.y; A1l0[2][1]=L1.z; A1l0[3][1]=L1.w;
        A1h1[0][0]=H2.x; A1h1[1][0]=H2.y; A1h1[2][0]=H2.z; A1h1[3][0]=H2.w;
        A1h1[0][1]=H3.x; A1h1[1][1]=H3.y; A1h1[2][1]=H3.z; A1h1[3][1]=H3.w;
        A1l1[0][0]=L2.x; A1l1[1][0]=L2.y; A1l1[2][0]=L2.z; A1l1[3][0]=L2.w;
        A1l1[0][1]=L3.x; A1l1[1][1]=L3.y; A1l1[2][1]=L3.z; A1l1[3][1]=L3.w;
    }

    float D0[3][4], D1[3][4];
    u32 Ah0[3][2], Al0[3][2], Ah1[3][2], Al1[3][2];

    // ---- layer 1 (K=32): B loaded once per nt, both mtiles ----
    #pragma unroll
    for (int nt = 0; nt < 3; nt++) {
        float q0 = b1s[nt * 8 + cq * 2], q1 = b1s[nt * 8 + cq * 2 + 1];
        D0[nt][0]=q0; D0[nt][1]=q1; D0[nt][2]=q0; D0[nt][3]=q1;
        D1[nt][0]=q0; D1[nt][1]=q1; D1[nt][2]=q0; D1[nt][3]=q1;
        u64 h0 = *(const u64*)(wsm + ((nt * 2 + 0) * 2 + 0) * 64 + lw * 2);
        u64 h1 = *(const u64*)(wsm + ((nt * 2 + 0) * 2 + 1) * 64 + lw * 2);
        u64 l0 = *(const u64*)(wsm + ((nt * 2 + 1) * 2 + 0) * 64 + lw * 2);
        u64 l1 = *(const u64*)(wsm + ((nt * 2 + 1) * 2 + 1) * 64 + lw * 2);
        u32 h00=(u32)h0, h01=(u32)(h0>>32), h10=(u32)h1, h11=(u32)(h1>>32);
        u32 l00=(u32)l0, l01=(u32)(l0>>32), l10=(u32)l1, l11=(u32)(l1>>32);
        mma16(D0[nt], A1h0[0][0],A1h0[0][1],A1h0[1][0],A1h0[1][1], h00,h01);
        mma16(D1[nt], A1h1[0][0],A1h1[0][1],A1h1[1][0],A1h1[1][1], h00,h01);
        mma16(D0[nt], A1h0[2][0],A1h0[2][1],A1h0[3][0],A1h0[3][1], h10,h11);
        mma16(D1[nt], A1h1[2][0],A1h1[2][1],A1h1[3][0],A1h1[3][1], h10,h11);
        mma16(D0[nt], A1l0[0][0],A1l0[0][1],A1l0[1][0],A1l0[1][1], h00,h01);
        mma16(D1[nt], A1l1[0][0],A1l1[0][1],A1l1[1][0],A1l1[1][1], h00,h01);
        mma16(D0[nt], A1l0[2][0],A1l0[2][1],A1l0[3][0],A1l0[3][1], h10,h11);
        mma16(D1[nt], A1l1[2][0],A1l1[2][1],A1l1[3][0],A1l1[3][1], h10,h11);
        mma16(D0[nt], A1h0[0][0],A1h0[0][1],A1h0[1][0],A1h0[1][1], l00,l01);
        mma16(D1[nt], A1h1[0][0],A1h1[0][1],A1h1[1][0],A1h1[1][1], l00,l01);
        mma16(D0[nt], A1h0[2][0],A1h0[2][1],A1h0[3][0],A1h0[3][1], l10,l11);
        mma16(D1[nt], A1h1[2][0],A1h1[2][1],A1h1[3][0],A1h1[3][1], l10,l11);
    }
    make_frags(D0, Ah0, Al0);
    make_frags(D1, Ah1, Al1);

    layer_hidden2(wsm, 768, 1152, b2s, lw, cq, Ah0, Al0, Ah1, Al1, D0, D1);   // layer 2
    make_frags(D0, Ah0, Al0);
    make_frags(D1, Ah1, Al1);
    layer_hidden2(wsm, 1344, 1728, b3s, lw, cq, Ah0, Al0, Ah1, Al1, D0, D1);  // layer 3
    make_frags(D0, Ah0, Al0);
    make_frags(D1, Ah1, Al1);

    // ---- layer 4: single n-tile (cols 0=s, 1=t), both mtiles ----
    float E0[4], E1[4];
    {
        float q0 = b4s[cq * 2], q1 = b4s[cq * 2 + 1];
        E0[0]=q0; E0[1]=q1; E0[2]=q0; E0[3]=q1;
        E1[0]=q0; E1[1]=q1; E1[2]=q0; E1[3]=q1;
        u64 ph = *(const u64*)(wsm + 1920 + lw * 2);
        u64 pl = *(const u64*)(wsm + 1920 + 64 + lw * 2);
        u32 c2h = wsm[2048 + lw], c2l = wsm[2048 + 32 + lw];
        u32 bh0 = (u32)ph, bh1 = (u32)(ph >> 32);
        u32 bl0 = (u32)pl, bl1 = (u32)(pl >> 32);
        mma16(E0, Ah0[0][0],Ah0[0][1],Ah0[1][0],Ah0[1][1], bh0,bh1);
        mma16(E1, Ah1[0][0],Ah1[0][1],Ah1[1][0],Ah1[1][1], bh0,bh1);
        mma8 (E0, Ah0[2][0],Ah0[2][1], c2h);
        mma8 (E1, Ah1[2][0],Ah1[2][1], c2h);
        mma16(E0, Al0[0][0],Al0[0][1],Al0[1][0],Al0[1][1], bh0,bh1);
        mma16(E1, Al1[0][0],Al1[0][1],Al1[1][0],Al1[1][1], bh0,bh1);
        mma8 (E0, Al0[2][0],Al0[2][1], c2h);
        mma8 (E1, Al1[2][0],Al1[2][1], c2h);
        mma16(E0, Ah0[0][0],Ah0[0][1],Ah0[1][0],Ah0[1][1], bl0,bl1);
        mma16(E1, Ah1[0][0],Ah1[0][1],Ah1[1][0],Ah1[1][1], bl0,bl1);
        mma8 (E0, Ah0[2][0],Ah0[2][1], c2l);
        mma8 (E1, Ah1[2][0],Ah1[2][1], c2l);
    }

    if (cq == 0) {
        const int kc = kidx + 1;
        const int rows[4] = { r0, r1, r2, r3 };
        const float sv[4] = { E0[0], E0[2], E1[0], E1[2] };
        const float tv[4] = { E0[1], E0[3], E1[1], E1[3] };
        #pragma unroll
        for (int q = 0; q < 4; q++) {
            int grow = tile + rows[q];
            float xv = x[grow * 32 + kc];
            z[grow * 32 + (30 - kidx)] = xv * expf(sv[q]) + tv[q];
            atomicAdd(&ld[grow], sv[q]);
        }
    }
}

extern "C" void kernel_launch(void* const* d_in, const int* in_sizes, int n_in,
                              void* d_out, int out_size) {
    const float* x  = (const float*)d_in[0];
    const float* p0 = (const float*)d_in[1];
    const float* W1 = (const float*)d_in[2];
    const float* b1 = (const float*)d_in[3];
    const float* W2 = (const float*)d_in[4];
    const float* b2 = (const float*)d_in[5];
    const float* W3 = (const float*)d_in[6];
    const float* b3 = (const float*)d_in[7];
    const float* W4 = (const float*)d_in[8];
    const float* b4 = (const float*)d_in[9];

    float* z  = (float*)d_out;                 // B*32
    float* ld = z + (size_t)BATCH * 32;        // B

    slowmaf_wprep_kernel<<<NK, THREADS>>>(W1, b1, W2, b2, W3, b3, W4, b4);
    slowmaf_xsplit_kernel<<<BATCH * 16 / 256, 256>>>(x);
    slowmaf_init_kernel<<<BATCH / 256, 256>>>(x, p0, z, ld);

    dim3 grid(BATCH / ROWS_CTA, NK);
    slowmaf_hmma_kernel<<<grid, THREADS>>>(x, z, ld);
}

// round 16
// speedup vs baseline: 1.5800x; 1.0489x over previous
#include <cuda_runtime.h>
#include <math.h>

// SlowMAF via warp-level bf16 mma.sync (m16n8k16/k8), 3-term hi/lo split.
// Round 12: 2 x-tiles per CTA (weight blob copied once, mainloop run twice),
// xsplit+init fused into one prepass kernel.
// Inputs (metadata order): x, p0, W1, b1, W2, b2, W3, b3, W4, b4
// Output: [ z (B*32 f32), log_det (B f32) ]

#define BATCH 65536
#define NK 31
#define THREADS 128
#define TILES_PER_CTA 2
#define ROWS_TILE 128     // 4 warps x 2 mtiles x 16 rows
#define WBLOB 2192        // u32 per k (layout map in wprep)

typedef unsigned int u32;
typedef unsigned long long u64;

__device__ u32 g_wblob[NK * WBLOB];
__device__ u32 g_xhi[(size_t)BATCH * 16];
__device__ u32 g_xlo[(size_t)BATCH * 16];

__device__ __forceinline__ void mma8(float d[4], u32 a0, u32 a1, u32 b) {
    asm("mma.sync.aligned.m16n8k8.row.col.f32.bf16.bf16.f32 "
        "{%0,%1,%2,%3}, {%4,%5}, {%6}, {%0,%1,%2,%3};"
        : "+f"(d[0]), "+f"(d[1]), "+f"(d[2]), "+f"(d[3])
        : "r"(a0), "r"(a1), "r"(b));
}
__device__ __forceinline__ void mma16(float d[4], u32 a0, u32 a1, u32 a2, u32 a3,
                                      u32 b0, u32 b1) {
    asm("mma.sync.aligned.m16n8k16.row.col.f32.bf16.bf16.f32 "
        "{%0,%1,%2,%3}, {%4,%5,%6,%7}, {%8,%9}, {%0,%1,%2,%3};"
        : "+f"(d[0]), "+f"(d[1]), "+f"(d[2]), "+f"(d[3])
        : "r"(a0), "r"(a1), "r"(a2), "r"(a3), "r"(b0), "r"(b1));
}

// Split f32 pair (v0=even, v1=odd) into packed bf16x2 hi (truncate) + lo (rn of remainder).
__device__ __forceinline__ void split_pair(float v0, float v1, u32& hi, u32& lo) {
    u32 b0 = __float_as_uint(v0), b1 = __float_as_uint(v1);
    asm("prmt.b32 %0, %1, %2, 0x7632;" : "=r"(hi) : "r"(b0), "r"(b1));
    float l0 = v0 - __uint_as_float(b0 & 0xFFFF0000u);
    float l1 = v1 - __uint_as_float(b1 & 0xFFFF0000u);
    asm("cvt.rn.bf16x2.f32 %0, %1, %2;" : "=r"(lo) : "f"(l1), "f"(l0));
}

__device__ __forceinline__ float lrelu(float v) { return fmaxf(v, 0.2f * v); }

__device__ __forceinline__ void make_frags(const float D[3][4], u32 Ah[3][2], u32 Al[3][2]) {
    #pragma unroll
    for (int nt = 0; nt < 3; nt++) {
        split_pair(lrelu(D[nt][0]), lrelu(D[nt][1]), Ah[nt][0], Al[nt][0]);
        split_pair(lrelu(D[nt][2]), lrelu(D[nt][3]), Ah[nt][1], Al[nt][1]);
    }
}

// ============ prepass: split + fragment-order weights ============
__global__ void slowmaf_wprep_kernel(
    const float* __restrict__ W1, const float* __restrict__ b1,
    const float* __restrict__ W2, const float* __restrict__ b2,
    const float* __restrict__ W3, const float* __restrict__ b3,
    const float* __restrict__ W4, const float* __restrict__ b4)
{
    const int k = blockIdx.x;
    const int tid = threadIdx.x;
    u32* blob = g_wblob + k * WBLOB;

    {   // W1: 3nt x 2cpair x 64
        const float* Wk = W1 + (size_t)k * (24 * 32);
        for (int e = tid; e < 3 * 2 * 64; e += THREADS) {
            int nt = e / 128, rem = e % 128;
            int cpair = rem / 64, r = rem % 64;
            int lw = r >> 1, half = r & 1;
            int c = cpair * 2 + half;
            int kk = lw >> 3, n = lw & 7;
            int k0 = c * 8 + kk * 2, ng = nt * 8 + n;
            u32 hi, lo; split_pair(Wk[ng * 32 + k0], Wk[ng * 32 + k0 + 1], hi, lo);
            blob[((nt * 2 + 0) * 2 + cpair) * 64 + r] = hi;
            blob[((nt * 2 + 1) * 2 + cpair) * 64 + r] = lo;
        }
    }
    {   // W2/W3 pairs (chunks 0,1) + chunk 2
        const float* Wk2 = W2 + (size_t)k * (24 * 24);
        const float* Wk3 = W3 + (size_t)k * (24 * 24);
        for (int e = tid; e < 3 * 64; e += THREADS) {
            int nt = e / 64, r = e % 64;
            int lw = r >> 1, c = r & 1;
            int kk = lw >> 3, n = lw & 7;
            int k0 = c * 8 + kk * 2, ng = nt * 8 + n;
            u32 hi, lo;
            split_pair(Wk2[ng * 24 + k0], Wk2[ng * 24 + k0 + 1], hi, lo);
            blob[768 + (nt * 2 + 0) * 64 + r] = hi;
            blob[768 + (nt * 2 + 1) * 64 + r] = lo;
            split_pair(Wk3[ng * 24 + k0], Wk3[ng * 24 + k0 + 1], hi, lo);
            blob[1344 + (nt * 2 + 0) * 64 + r] = hi;
            blob[1344 + (nt * 2 + 1) * 64 + r] = lo;
        }
        for (int e = tid; e < 3 * 32; e += THREADS) {
            int nt = e / 32, lw = e % 32;
            int kk = lw >> 3, n = lw & 7;
            int k0 = 16 + kk * 2, ng = nt * 8 + n;
            u32 hi, lo;
            split_pair(Wk2[ng * 24 + k0], Wk2[ng * 24 + k0 + 1], hi, lo);
            blob[1152 + (nt * 2 + 0) * 32 + lw] = hi;
            blob[1152 + (nt * 2 + 1) * 32 + lw] = lo;
            split_pair(Wk3[ng * 24 + k0], Wk3[ng * 24 + k0 + 1], hi, lo);
            blob[1728 + (nt * 2 + 0) * 32 + lw] = hi;
            blob[1728 + (nt * 2 + 1) * 32 + lw] = lo;
        }
    }
    {   // W4
        const float* Wk4 = W4 + (size_t)k * (2 * 24);
        for (int e = tid; e < 64; e += THREADS) {
            int lw = e >> 1, c = e & 1;
            int kk = lw >> 3, n = lw & 7;
            int k0 = c * 8 + kk * 2;
            float w0 = (n < 2) ? Wk4[n * 24 + k0] : 0.0f;
            float w1v = (n < 2) ? Wk4[n * 24 + k0 + 1] : 0.0f;
            u32 hi, lo; split_pair(w0, w1v, hi, lo);
            blob[1920 + e] = hi;
            blob[1920 + 64 + e] = lo;
        }
        for (int e = tid; e < 32; e += THREADS) {
            int kk = e >> 3, n = e & 7;
            int k0 = 16 + kk * 2;
            float w0 = (n < 2) ? Wk4[n * 24 + k0] : 0.0f;
            float w1v = (n < 2) ? Wk4[n * 24 + k0 + 1] : 0.0f;
            u32 hi, lo; split_pair(w0, w1v, hi, lo);
            blob[2048 + e] = hi;
            blob[2048 + 32 + e] = lo;
        }
    }
    float* fb = (float*)(blob + 2112);
    if (tid < 24) {
        fb[tid]      = b1[k * 24 + tid];
        fb[24 + tid] = b2[k * 24 + tid];
        fb[48 + tid] = b3[k * 24 + tid];
    }
    if (tid < 8) fb[72 + tid] = (tid < 2) ? b4[k * 2 + tid] : 0.0f;
}

// ---- fused prepass: split x into hi/lo + handle dim-0 (LeafParam) output ----
__global__ void slowmaf_xinit_kernel(const float* __restrict__ x,
                                     const float* __restrict__ p0,
                                     float* __restrict__ z,
                                     float* __restrict__ ld) {
    int p = blockIdx.x * blockDim.x + threadIdx.x;   // < BATCH*16
    int row = p >> 4, cp = p & 15;
    float2 xv = ((const float2*)x)[p];
    u32 hi, lo; split_pair(xv.x, xv.y, hi, lo);
    int dst = (row << 4) + ((cp & 3) << 2) + (cp >> 2);
    g_xhi[dst] = hi;
    g_xlo[dst] = lo;
    if (cp == 0) {
        float s0 = p0[0];
        z[row * 32 + 31] = xv.x * expf(s0) + p0[1];  // order[0] = 31
        ld[row] = s0;
    }
}

// hidden layer (K=24), BOTH mtiles, B loaded once per nt.
__device__ __forceinline__ void layer_hidden2(
    const u32* wsm, int pairBase, int c2Base, const float* bs, int lw, int cq,
    const u32 Ah0[3][2], const u32 Al0[3][2],
    const u32 Ah1[3][2], const u32 Al1[3][2],
    float D0[3][4], float D1[3][4])
{
    #pragma unroll
    for (int nt = 0; nt < 3; nt++) {
        float q0 = bs[nt * 8 + cq * 2], q1 = bs[nt * 8 + cq * 2 + 1];
        D0[nt][0] = q0; D0[nt][1] = q1; D0[nt][2] = q0; D0[nt][3] = q1;
        D1[nt][0] = q0; D1[nt][1] = q1; D1[nt][2] = q0; D1[nt][3] = q1;
        u64 ph = *(const u64*)(wsm + pairBase + (nt * 2 + 0) * 64 + lw * 2);
        u64 pl = *(const u64*)(wsm + pairBase + (nt * 2 + 1) * 64 + lw * 2);
        u32 c2h = wsm[c2Base + (nt * 2 + 0) * 32 + lw];
        u32 c2l = wsm[c2Base + (nt * 2 + 1) * 32 + lw];
        u32 bh0 = (u32)ph, bh1 = (u32)(ph >> 32);
        u32 bl0 = (u32)pl, bl1 = (u32)(pl >> 32);
        mma16(D0[nt], Ah0[0][0], Ah0[0][1], Ah0[1][0], Ah0[1][1], bh0, bh1);
        mma16(D1[nt], Ah1[0][0], Ah1[0][1], Ah1[1][0], Ah1[1][1], bh0, bh1);
        mma8 (D0[nt], Ah0[2][0], Ah0[2][1], c2h);
        mma8 (D1[nt], Ah1[2][0], Ah1[2][1], c2h);
        mma16(D0[nt], Al0[0][0], Al0[0][1], Al0[1][0], Al0[1][1], bh0, bh1);
        mma16(D1[nt], Al1[0][0], Al1[0][1], Al1[1][0], Al1[1][1], bh0, bh1);
        mma8 (D0[nt], Al0[2][0], Al0[2][1], c2h);
        mma8 (D1[nt], Al1[2][0], Al1[2][1], c2h);
        mma16(D0[nt], Ah0[0][0], Ah0[0][1], Ah0[1][0], Ah0[1][1], bl0, bl1);
        mma16(D1[nt], Ah1[0][0], Ah1[0][1], Ah1[1][0], Ah1[1][1], bl0, bl1);
        mma8 (D0[nt], Ah0[2][0], Ah0[2][1], c2l);
        mma8 (D1[nt], Ah1[2][0], Ah1[2][1], c2l);
    }
}

__global__ __launch_bounds__(THREADS, 5) void slowmaf_hmma_kernel(
    const float* __restrict__ x, float* __restrict__ z, float* __restrict__ ld)
{
    __shared__ __align__(16) u32 wsm[WBLOB];

    const int kidx = blockIdx.y;                 // 0..30
    const int tid  = threadIdx.x;

    {   // copy pre-split weight blob (548 uint4) — ONCE per CTA
        const uint4* src = (const uint4*)(g_wblob + kidx * WBLOB);
        uint4* dst = (uint4*)wsm;
        #pragma unroll
        for (int i = 0; i < 5; i++) {
            int e = i * THREADS + tid;
            if (e < WBLOB / 4) dst[e] = src[e];
        }
    }
    __syncthreads();

    const float* fb  = (const float*)(wsm + 2112);
    const float* b1s = fb, *b2s = fb + 24, *b3s = fb + 48, *b4s = fb + 72;

    const int warp = tid >> 5, lane = tid & 31;
    const int qr = lane >> 2;        // row-in-8 (B-frag n)
    const int cq = lane & 3;         // colpair  (B-frag kk)
    const int lw = cq * 8 + qr;

    const int rb = warp * 32;
    const int r0 = rb + qr,      r1 = r0 + 8;     // mtile 0
    const int r2 = rb + 16 + qr, r3 = r2 + 8;     // mtile 1

    #pragma unroll 1
    for (int it = 0; it < TILES_PER_CTA; it++) {
        const int tile = (blockIdx.x * TILES_PER_CTA + it) * ROWS_TILE;

        // ---- A fragments for layer 1, both mtiles ----
        u32 A1h0[4][2], A1l0[4][2], A1h1[4][2], A1l1[4][2];
        {
            const size_t g0 = ((size_t)(tile + r0) << 4) + (cq << 2);
            const size_t g1 = ((size_t)(tile + r1) << 4) + (cq << 2);
            const size_t g2 = ((size_t)(tile + r2) << 4) + (cq << 2);
            const size_t g3 = ((size_t)(tile + r3) << 4) + (cq << 2);
            uint4 H0 = *(const uint4*)(g_xhi + g0), H1 = *(const uint4*)(g_xhi + g1);
            uint4 L0 = *(const uint4*)(g_xlo + g0), L1 = *(const uint4*)(g_xlo + g1);
            uint4 H2 = *(const uint4*)(g_xhi + g2), H3 = *(const uint4*)(g_xhi + g3);
            uint4 L2 = *(const uint4*)(g_xlo + g2), L3 = *(const uint4*)(g_xlo + g3);
            A1h0[0][0]=H0.x; A1h0[1][0]=H0.y; A1h0[2][0]=H0.z; A1h0[3][0]=H0.w;
            A1h0[0][1]=H1.x; A1h0[1][1]=H1.y; A1h0[2][1]=H1.z; A1h0[3][1]=H1.w;
            A1l0[0][0]=L0.x; A1l0[1][0]=L0.y; A1l0[2][0]=L0.z; A1l0[3][0]=L0.w;
            A1l0[0][1]=L1.x; A1l0[1][1]=L1.y; A1l0[2][1]=L1.z; A1l0[3][1]=L1.w;
            A1h1[0][0]=H2.x; A1h1[1][0]=H2.y; A1h1[2][0]=H2.z; A1h1[3][0]=H2.w;
            A1h1[0][1]=H3.x; A1h1[1][1]=H3.y; A1h1[2][1]=H3.z; A1h1[3][1]=H3.w;
            A1l1[0][0]=L2.x; A1l1[1][0]=L2.y; A1l1[2][0]=L2.z; A1l1[3][0]=L2.w;
            A1l1[0][1]=L3.x; A1l1[1][1]=L3.y; A1l1[2][1]=L3.z; A1l1[3][1]=L3.w;
        }

        float D0[3][4], D1[3][4];
        u32 Ah0[3][2], Al0[3][2], Ah1[3][2], Al1[3][2];

        // ---- layer 1 (K=32): B loaded once per nt, both mtiles ----
        #pragma unroll
        for (int nt = 0; nt < 3; nt++) {
            float q0 = b1s[nt * 8 + cq * 2], q1 = b1s[nt * 8 + cq * 2 + 1];
            D0[nt][0]=q0; D0[nt][1]=q1; D0[nt][2]=q0; D0[nt][3]=q1;
            D1[nt][0]=q0; D1[nt][1]=q1; D1[nt][2]=q0; D1[nt][3]=q1;
            u64 h0 = *(const u64*)(wsm + ((nt * 2 + 0) * 2 + 0) * 64 + lw * 2);
            u64 h1 = *(const u64*)(wsm + ((nt * 2 + 0) * 2 + 1) * 64 + lw * 2);
            u64 l0 = *(const u64*)(wsm + ((nt * 2 + 1) * 2 + 0) * 64 + lw * 2);
            u64 l1 = *(const u64*)(wsm + ((nt * 2 + 1) * 2 + 1) * 64 + lw * 2);
            u32 h00=(u32)h0, h01=(u32)(h0>>32), h10=(u32)h1, h11=(u32)(h1>>32);
            u32 l00=(u32)l0, l01=(u32)(l0>>32), l10=(u32)l1, l11=(u32)(l1>>32);
            mma16(D0[nt], A1h0[0][0],A1h0[0][1],A1h0[1][0],A1h0[1][1], h00,h01);
            mma16(D1[nt], A1h1[0][0],A1h1[0][1],A1h1[1][0],A1h1[1][1], h00,h01);
            mma16(D0[nt], A1h0[2][0],A1h0[2][1],A1h0[3][0],A1h0[3][1], h10,h11);
            mma16(D1[nt], A1h1[2][0],A1h1[2][1],A1h1[3][0],A1h1[3][1], h10,h11);
            mma16(D0[nt], A1l0[0][0],A1l0[0][1],A1l0[1][0],A1l0[1][1], h00,h01);
            mma16(D1[nt], A1l1[0][0],A1l1[0][1],A1l1[1][0],A1l1[1][1], h00,h01);
            mma16(D0[nt], A1l0[2][0],A1l0[2][1],A1l0[3][0],A1l0[3][1], h10,h11);
            mma16(D1[nt], A1l1[2][0],A1l1[2][1],A1l1[3][0],A1l1[3][1], h10,h11);
            mma16(D0[nt], A1h0[0][0],A1h0[0][1],A1h0[1][0],A1h0[1][1], l00,l01);
            mma16(D1[nt], A1h1[0][0],A1h1[0][1],A1h1[1][0],A1h1[1][1], l00,l01);
            mma16(D0[nt], A1h0[2][0],A1h0[2][1],A1h0[3][0],A1h0[3][1], l10,l11);
            mma16(D1[nt], A1h1[2][0],A1h1[2][1],A1h1[3][0],A1h1[3][1], l10,l11);
        }
        make_frags(D0, Ah0, Al0);
        make_frags(D1, Ah1, Al1);

        layer_hidden2(wsm, 768, 1152, b2s, lw, cq, Ah0, Al0, Ah1, Al1, D0, D1);   // layer 2
        make_frags(D0, Ah0, Al0);
        make_frags(D1, Ah1, Al1);
        layer_hidden2(wsm, 1344, 1728, b3s, lw, cq, Ah0, Al0, Ah1, Al1, D0, D1);  // layer 3
        make_frags(D0, Ah0, Al0);
        make_frags(D1, Ah1, Al1);

        // ---- layer 4: single n-tile (cols 0=s, 1=t), both mtiles ----
        float E0[4], E1[4];
        {
            float q0 = b4s[cq * 2], q1 = b4s[cq * 2 + 1];
            E0[0]=q0; E0[1]=q1; E0[2]=q0; E0[3]=q1;
            E1[0]=q0; E1[1]=q1; E1[2]=q0; E1[3]=q1;
            u64 ph = *(const u64*)(wsm + 1920 + lw * 2);
            u64 pl = *(const u64*)(wsm + 1920 + 64 + lw * 2);
            u32 c2h = wsm[2048 + lw], c2l = wsm[2048 + 32 + lw];
            u32 bh0 = (u32)ph, bh1 = (u32)(ph >> 32);
            u32 bl0 = (u32)pl, bl1 = (u32)(pl >> 32);
            mma16(E0, Ah0[0][0],Ah0[0][1],Ah0[1][0],Ah0[1][1], bh0,bh1);
            mma16(E1, Ah1[0][0],Ah1[0][1],Ah1[1][0],Ah1[1][1], bh0,bh1);
            mma8 (E0, Ah0[2][0],Ah0[2][1], c2h);
            mma8 (E1, Ah1[2][0],Ah1[2][1], c2h);
            mma16(E0, Al0[0][0],Al0[0][1],Al0[1][0],Al0[1][1], bh0,bh1);
            mma16(E1, Al1[0][0],Al1[0][1],Al1[1][0],Al1[1][1], bh0,bh1);
            mma8 (E0, Al0[2][0],Al0[2][1], c2h);
            mma8 (E1, Al1[2][0],Al1[2][1], c2h);
            mma16(E0, Ah0[0][0],Ah0[0][1],Ah0[1][0],Ah0[1][1], bl0,bl1);
            mma16(E1, Ah1[0][0],Ah1[0][1],Ah1[1][0],Ah1[1][1], bl0,bl1);
            mma8 (E0, Ah0[2][0],Ah0[2][1], c2l);
            mma8 (E1, Ah1[2][0],Ah1[2][1], c2l);
        }

        if (cq == 0) {
            const int kc = kidx + 1;
            const int rows[4] = { r0, r1, r2, r3 };
            const float sv[4] = { E0[0], E0[2], E1[0], E1[2] };
            const float tv[4] = { E0[1], E0[3], E1[1], E1[3] };
            #pragma unroll
            for (int q = 0; q < 4; q++) {
                int grow = tile + rows[q];
                float xv = x[grow * 32 + kc];
                z[grow * 32 + (30 - kidx)] = xv * expf(sv[q]) + tv[q];
                atomicAdd(&ld[grow], sv[q]);
            }
        }
    }
}

extern "C" void kernel_launch(void* const* d_in, const int* in_sizes, int n_in,
                              void* d_out, int out_size) {
    const float* x  = (const float*)d_in[0];
    const float* p0 = (const float*)d_in[1];
    const float* W1 = (const float*)d_in[2];
    const float* b1 = (const float*)d_in[3];
    const float* W2 = (const float*)d_in[4];
    const float* b2 = (const float*)d_in[5];
    const float* W3 = (const float*)d_in[6];
    const float* b3 = (const float*)d_in[7];
    const float* W4 = (const float*)d_in[8];
    const float* b4 = (const float*)d_in[9];

    float* z  = (float*)d_out;                 // B*32
    float* ld = z + (size_t)BATCH * 32;        // B

    slowmaf_wprep_kernel<<<NK, THREADS>>>(W1, b1, W2, b2, W3, b3, W4, b4);
    slowmaf_xinit_kernel<<<BATCH * 16 / 256, 256>>>(x, p0, z, ld);

    dim3 grid(BATCH / (ROWS_TILE * TILES_PER_CTA), NK);
    slowmaf_hmma_kernel<<<grid, THREADS>>>(x, z, ld);
}